// round 16
// baseline (speedup 1.0000x reference)
#include <cuda_runtime.h>
#include <cstdint>

// TaylorActivation: out = Horner(x; c[0..8]), elementwise over 512x65536 fp32.
// HBM/LTS-bound stream: 128 MiB in + 128 MiB out.
//
// R14: Blackwell 256-bit vector ld/st (ld/st.global.v8.f32 — sm_100+ only,
//      PTX-only like FFMA2) to halve LDG/STG issue count and L1tex dispatch.
//      2x v8 per thread (64B), front-batched; FFMA2 packed Horner.

__device__ __forceinline__ uint64_t pack2(float lo, float hi) {
    uint64_t r;
    asm("mov.b64 %0, {%1, %2};" : "=l"(r) : "f"(lo), "f"(hi));
    return r;
}

__device__ __forceinline__ uint64_t fma2(uint64_t a, uint64_t b, uint64_t c) {
    uint64_t d;
    asm("fma.rn.f32x2 %0, %1, %2, %3;" : "=l"(d) : "l"(a), "l"(b), "l"(c));
    return d;
}

__device__ __forceinline__ void ldg_v8(const float* p, float r[8]) {
    asm("ld.global.v8.f32 {%0,%1,%2,%3,%4,%5,%6,%7}, [%8];"
        : "=f"(r[0]), "=f"(r[1]), "=f"(r[2]), "=f"(r[3]),
          "=f"(r[4]), "=f"(r[5]), "=f"(r[6]), "=f"(r[7])
        : "l"(p));
}

__device__ __forceinline__ void stg_v8(float* p, const float r[8]) {
    asm volatile("st.global.v8.f32 [%0], {%1,%2,%3,%4,%5,%6,%7,%8};"
        :: "l"(p),
           "f"(r[0]), "f"(r[1]), "f"(r[2]), "f"(r[3]),
           "f"(r[4]), "f"(r[5]), "f"(r[6]), "f"(r[7])
        : "memory");
}

__global__ void __launch_bounds__(256)
taylor_kernel(const float* __restrict__ x,
              const float* __restrict__ w,
              float* __restrict__ out)
{
    // Index in units of 8 floats (32 B). Each block: 256 thr * 2 chunks.
    long long idx8 = (long long)blockIdx.x * (256 * 2) + threadIdx.x;

    // Front-batched 256-bit loads (2 per thread, independent).
    float v0[8], v1[8];
    ldg_v8(x + (idx8 + 0 * 256) * 8, v0);
    ldg_v8(x + (idx8 + 1 * 256) * 8, v1);

    // 9 coefficients via 3 broadcast loads.
    const float4 wa = __ldg((const float4*)&w[0]);  // c0..c3
    const float4 wb = __ldg((const float4*)&w[4]);  // c4..c7
    const float  c8 = __ldg(&w[8]);

    const uint64_t p0 = pack2(wa.x, wa.x), p1 = pack2(wa.y, wa.y);
    const uint64_t p2 = pack2(wa.z, wa.z), p3 = pack2(wa.w, wa.w);
    const uint64_t p4 = pack2(wb.x, wb.x), p5 = pack2(wb.y, wb.y);
    const uint64_t p6 = pack2(wb.z, wb.z), p7 = pack2(wb.w, wb.w);
    const uint64_t p8 = pack2(c8, c8);

    // Pack each v8 into 4 f32x2 lanes.
    uint64_t a0 = pack2(v0[0], v0[1]), a1 = pack2(v0[2], v0[3]);
    uint64_t a2 = pack2(v0[4], v0[5]), a3 = pack2(v0[6], v0[7]);
    uint64_t b0 = pack2(v1[0], v1[1]), b1 = pack2(v1[2], v1[3]);
    uint64_t b2 = pack2(v1[4], v1[5]), b3 = pack2(v1[6], v1[7]);

    uint64_t ra0 = p8, ra1 = p8, ra2 = p8, ra3 = p8;
    uint64_t rb0 = p8, rb1 = p8, rb2 = p8, rb3 = p8;

#define STEP(pk)                                          \
    ra0 = fma2(ra0, a0, pk); ra1 = fma2(ra1, a1, pk);     \
    ra2 = fma2(ra2, a2, pk); ra3 = fma2(ra3, a3, pk);     \
    rb0 = fma2(rb0, b0, pk); rb1 = fma2(rb1, b1, pk);     \
    rb2 = fma2(rb2, b2, pk); rb3 = fma2(rb3, b3, pk);

    STEP(p7) STEP(p6) STEP(p5) STEP(p4)
    STEP(p3) STEP(p2) STEP(p1) STEP(p0)
#undef STEP

    // Unpack packed accumulators directly into store arrays.
    float r0[8], r1[8];
    asm("mov.b64 {%0, %1}, %2;" : "=f"(r0[0]), "=f"(r0[1]) : "l"(ra0));
    asm("mov.b64 {%0, %1}, %2;" : "=f"(r0[2]), "=f"(r0[3]) : "l"(ra1));
    asm("mov.b64 {%0, %1}, %2;" : "=f"(r0[4]), "=f"(r0[5]) : "l"(ra2));
    asm("mov.b64 {%0, %1}, %2;" : "=f"(r0[6]), "=f"(r0[7]) : "l"(ra3));
    asm("mov.b64 {%0, %1}, %2;" : "=f"(r1[0]), "=f"(r1[1]) : "l"(rb0));
    asm("mov.b64 {%0, %1}, %2;" : "=f"(r1[2]), "=f"(r1[3]) : "l"(rb1));
    asm("mov.b64 {%0, %1}, %2;" : "=f"(r1[4]), "=f"(r1[5]) : "l"(rb2));
    asm("mov.b64 {%0, %1}, %2;" : "=f"(r1[6]), "=f"(r1[7]) : "l"(rb3));

    stg_v8(out + (idx8 + 0 * 256) * 8, r0);
    stg_v8(out + (idx8 + 1 * 256) * 8, r1);
}

extern "C" void kernel_launch(void* const* d_in, const int* in_sizes, int n_in,
                              void* d_out, int out_size)
{
    const float* x = (const float*)d_in[0];   // (512, 65536) fp32
    const float* w = (const float*)d_in[1];   // (9, 1) fp32
    float* out = (float*)d_out;

    int n = in_sizes[0];            // 33554432
    int n8 = n / 8;                 // 4194304 float8 chunks
    int blocks = n8 / (256 * 2);    // 8192 (exact)

    taylor_kernel<<<blocks, 256>>>(x, w, out);
}

// round 17
// speedup vs baseline: 1.0345x; 1.0345x over previous
#include <cuda_runtime.h>
#include <cstdint>

// TaylorActivation: out = Horner(x; c[0..8]), elementwise over 512x65536 fp32.
// HBM-bound stream: 128 MiB in + 128 MiB out. Plateau measured at ~5.96 TB/s.
//
// R16: best-measured body (R13: 2x float4/thread, FFMA2 packed Horner,
//      3 vectorized coeff LDGs, 16384x256) + st.global.cs on OUTPUT only
//      (streaming writeback: drain dirty lines early/batched, keep L2 ways
//      for inbound read sectors; load hints stay default — they hurt in R4).

__device__ __forceinline__ uint64_t pack2(float lo, float hi) {
    uint64_t r;
    asm("mov.b64 %0, {%1, %2};" : "=l"(r) : "f"(lo), "f"(hi));
    return r;
}

__device__ __forceinline__ void unpack2(uint64_t v, float& lo, float& hi) {
    asm("mov.b64 {%0, %1}, %2;" : "=f"(lo), "=f"(hi) : "l"(v));
}

__device__ __forceinline__ uint64_t fma2(uint64_t a, uint64_t b, uint64_t c) {
    uint64_t d;
    asm("fma.rn.f32x2 %0, %1, %2, %3;" : "=l"(d) : "l"(a), "l"(b), "l"(c));
    return d;
}

__global__ void __launch_bounds__(256)
taylor_kernel(const float4* __restrict__ x,
              const float* __restrict__ w,
              float4* __restrict__ out)
{
    int base = blockIdx.x * (256 * 2) + threadIdx.x;

    // Front-batched independent loads (default cache op — best measured).
    float4 v0 = x[base + 0 * 256];
    float4 v1 = x[base + 1 * 256];

    // 9 coefficients via 3 broadcast loads (L1-resident after first warp).
    const float4 wa = __ldg((const float4*)&w[0]);  // c0..c3
    const float4 wb = __ldg((const float4*)&w[4]);  // c4..c7
    const float  c8 = __ldg(&w[8]);

    const uint64_t p0 = pack2(wa.x, wa.x), p1 = pack2(wa.y, wa.y);
    const uint64_t p2 = pack2(wa.z, wa.z), p3 = pack2(wa.w, wa.w);
    const uint64_t p4 = pack2(wb.x, wb.x), p5 = pack2(wb.y, wb.y);
    const uint64_t p6 = pack2(wb.z, wb.z), p7 = pack2(wb.w, wb.w);
    const uint64_t p8 = pack2(c8, c8);

    uint64_t a0 = pack2(v0.x, v0.y), b0 = pack2(v0.z, v0.w);
    uint64_t a1 = pack2(v1.x, v1.y), b1 = pack2(v1.z, v1.w);

    uint64_t ra0 = p8, rb0 = p8;
    uint64_t ra1 = p8, rb1 = p8;

#define STEP(pk)                                      \
    ra0 = fma2(ra0, a0, pk); rb0 = fma2(rb0, b0, pk); \
    ra1 = fma2(ra1, a1, pk); rb1 = fma2(rb1, b1, pk);

    STEP(p7) STEP(p6) STEP(p5) STEP(p4)
    STEP(p3) STEP(p2) STEP(p1) STEP(p0)
#undef STEP

    float4 r;
    unpack2(ra0, r.x, r.y); unpack2(rb0, r.z, r.w);
    __stcs(&out[base + 0 * 256], r);
    unpack2(ra1, r.x, r.y); unpack2(rb1, r.z, r.w);
    __stcs(&out[base + 1 * 256], r);
}

extern "C" void kernel_launch(void* const* d_in, const int* in_sizes, int n_in,
                              void* d_out, int out_size)
{
    const float* x = (const float*)d_in[0];   // (512, 65536) fp32
    const float* w = (const float*)d_in[1];   // (9, 1) fp32
    float* out = (float*)d_out;

    int n = in_sizes[0];          // 33554432
    int n4 = n / 4;               // 8388608 float4
    int blocks = n4 / (256 * 2);  // 16384 (exact)

    taylor_kernel<<<blocks, 256>>>(
        (const float4*)x, w, (float4*)out);
}